// round 9
// baseline (speedup 1.0000x reference)
#include <cuda_runtime.h>
#include <cuda_bf16.h>
#include <math.h>

// ---------------------------------------------------------------------------
// Seq2Seq LSTM (B=64, S=1024, T=512, H=512, D_IN=D_OUT=32), fp32.
// Persistent kernel: 128 CTAs x 512 threads, all-to-all flag grid barrier.
// Each CTA owns 16 gate-rows (4 units x 4 gates) x 64 batches per layer-tile.
// Encoder phases merged (L1(t-1)+L0(t) in one barrier). Decoder unmerged.
// Dual-term fused K-loop: prefetch flows across the GEMM-term boundary.
// Decoder feedback GEMM folded into precomputed gM = dec_Wih0 @ out_W.
// ---------------------------------------------------------------------------

#define NB   128
#define NT   512
#define B_    64
#define H_    512
#define G4   2048
#define DIN   32
#define SLEN 1024
#define TLEN  512

#define BUFW 12                       // floats per batch row in stage buffer
#define BUFSZ (64 * BUFW)             // 768 floats per warp
#define REDBASE (16 * BUFSZ)          // 12288 floats
#define RROW  1042                    // unmerged reduction row stride
#define RROW2 520                     // merged reduction row stride (bank-exact)
#define SMEM_FLOATS (REDBASE + 16 * RROW)     // >= REDBASE + 32*RROW2
#define SMEM_BYTES  (SMEM_FLOATS * 4)         // 115840 B

struct P {
    const float *src;
    const float *eWih0, *eWhh0, *ebih0, *ebhh0;
    const float *eWih1, *eWhh1, *ebih1, *ebhh1;
    const float *dWih0, *dWhh0, *dbih0, *dbhh0;
    const float *dWih1, *dWhh1, *dbih1, *dbhh1;
    const float *outW, *outB;
    float *out;
};

// ---- persistent state (device globals; allocation-free scratch) ----
__device__ float gH0[2][B_ * H_];
__device__ float gH1[2][B_ * H_];
__device__ float gC0[B_ * H_];
__device__ float gC1[B_ * H_];
__device__ float gM[G4 * H_];      // dec_Wih0 @ out_W   [2048 x 512]
__device__ float gB2[G4];          // dec_Wih0 @ out_b
__device__ unsigned gFlag[NB];     // monotonic per-CTA arrival counters

// All-to-all grid barrier: each CTA publishes its epoch, then 128 threads
// poll all 128 flags in parallel. One L2 round-trip after last arrival.
__device__ __forceinline__ void grid_bar(unsigned &bgen) {
    __threadfence();
    __syncthreads();
    bgen++;
    if (threadIdx.x == 0)
        ((volatile unsigned*)gFlag)[blockIdx.x] = bgen;
    if (threadIdx.x < NB) {
        volatile unsigned* f = gFlag + threadIdx.x;
        while (*f < bgen) __nanosleep(32);
    }
    __threadfence();
    __syncthreads();
}

__device__ __forceinline__ float sigm(float x) { return 1.0f / (1.0f + expf(-x)); }

__device__ __forceinline__ float fma4(float4 a, float4 b, float s) {
    return fmaf(a.x, b.x, fmaf(a.y, b.y, fmaf(a.z, b.z, fmaf(a.w, b.w, s))));
}

__device__ __forceinline__ void ld4x(const float* g0, const float* g1,
                                     const float* g2, const float* g3, bool cg,
                                     float4 &p0, float4 &p1, float4 &p2, float4 &p3)
{
    if (cg) {
        p0 = __ldcg((const float4*)g0); p1 = __ldcg((const float4*)g1);
        p2 = __ldcg((const float4*)g2); p3 = __ldcg((const float4*)g3);
    } else {
        p0 = __ldg((const float4*)g0);  p1 = __ldg((const float4*)g1);
        p2 = __ldg((const float4*)g2);  p3 = __ldg((const float4*)g3);
    }
}

// Fused dual-term GEMM: nA chunks (8 k each) from (xA, WA) then nB chunks
// from (xB, WB), one continuous loop; prefetch crosses the term boundary.
// Accumulates acc[4 rows][8 batches]. W* row stride = 512, pre-offset to row0.
__device__ __forceinline__ void term_dual(
    const float* xA, int ldA, const float* __restrict__ WA, bool cgA, int kbA, int nA,
    const float* xB, int ldB, const float* __restrict__ WB, bool cgB, int kbB, int nB,
    int lane, int bq, float acc[4][8], float* buf)
{
    const int j0 = lane, j1 = 32 + lane, j2 = 64 + lane, j3 = 96 + lane;
    const int b0 = j0 >> 1, b1 = j1 >> 1, b2_ = j2 >> 1, b3 = j3 >> 1;
    const int q0 = (j0 & 1) << 2, q1 = (j1 & 1) << 2, q2 = (j2 & 1) << 2, q3 = (j3 & 1) << 2;
    const int ntot = nA + nB;

    float4 pf0, pf1, pf2, pf3;
    {   // fetch chunk 0
        const float* x; int ld, off; bool cg;
        if (0 < nA) { x = xA; ld = ldA; off = kbA; cg = cgA; }
        else        { x = xB; ld = ldB; off = kbB; cg = cgB; }
        ld4x(x + b0 * ld + off + q0, x + b1 * ld + off + q1,
             x + b2_ * ld + off + q2, x + b3 * ld + off + q3, cg,
             pf0, pf1, pf2, pf3);
    }
    for (int c = 0; c < ntot; c++) {
        __syncwarp();                      // prior chunk fully consumed
        *(float4*)(buf + b0 * BUFW + q0) = pf0;
        *(float4*)(buf + b1 * BUFW + q1) = pf1;
        *(float4*)(buf + b2_ * BUFW + q2) = pf2;
        *(float4*)(buf + b3 * BUFW + q3) = pf3;
        if (c + 1 < ntot) {                // prefetch next chunk under compute
            const int cn = c + 1;
            const float* x; int ld, off; bool cg;
            if (cn < nA) { x = xA; ld = ldA; off = kbA + cn * 8;        cg = cgA; }
            else         { x = xB; ld = ldB; off = kbB + (cn - nA) * 8; cg = cgB; }
            ld4x(x + b0 * ld + off + q0, x + b1 * ld + off + q1,
                 x + b2_ * ld + off + q2, x + b3 * ld + off + q3, cg,
                 pf0, pf1, pf2, pf3);
        }
        __syncwarp();                      // staged data visible
        const float* wb = (c < nA) ? (WA + kbA + c * 8)
                                   : (WB + kbB + (c - nA) * 8);
        const float* hb = buf + bq * BUFW;
        #pragma unroll
        for (int kk = 0; kk < 8; kk += 4) {
            float4 wv0 = __ldg((const float4*)(wb + 0 * H_ + kk));
            float4 wv1 = __ldg((const float4*)(wb + 1 * H_ + kk));
            float4 wv2 = __ldg((const float4*)(wb + 2 * H_ + kk));
            float4 wv3 = __ldg((const float4*)(wb + 3 * H_ + kk));
            #pragma unroll
            for (int m = 0; m < 8; m++) {
                float4 hv = *(const float4*)(hb + m * (8 * BUFW) + kk);
                acc[0][m] = fma4(wv0, hv, acc[0][m]);
                acc[1][m] = fma4(wv1, hv, acc[1][m]);
                acc[2][m] = fma4(wv2, hv, acc[2][m]);
                acc[3][m] = fma4(wv3, hv, acc[3][m]);
            }
        }
    }
    __syncwarp();
}

// K=32 term, 16 segments (unmerged): warp takes 2 k columns.
__device__ __forceinline__ void term32w2(
    const float* __restrict__ x, int ld, const float* __restrict__ Wrow0,
    int seg, int lane, int bq, float acc[4][8], float* buf)
{
    const int kbase = seg * 2;
    __syncwarp();
    #pragma unroll
    for (int i = 0; i < 2; i++) {
        int b = lane + (i << 5);
        float2 v = __ldg((const float2*)(x + b * ld + kbase));
        *(float2*)(buf + b * BUFW) = v;
    }
    __syncwarp();
    float2 w0 = __ldg((const float2*)(Wrow0 + 0 * DIN + kbase));
    float2 w1 = __ldg((const float2*)(Wrow0 + 1 * DIN + kbase));
    float2 w2 = __ldg((const float2*)(Wrow0 + 2 * DIN + kbase));
    float2 w3 = __ldg((const float2*)(Wrow0 + 3 * DIN + kbase));
    #pragma unroll
    for (int m = 0; m < 8; m++) {
        float2 hv = *(const float2*)(buf + ((m << 3) + bq) * BUFW);
        acc[0][m] = fmaf(w0.x, hv.x, fmaf(w0.y, hv.y, acc[0][m]));
        acc[1][m] = fmaf(w1.x, hv.x, fmaf(w1.y, hv.y, acc[1][m]));
        acc[2][m] = fmaf(w2.x, hv.x, fmaf(w2.y, hv.y, acc[2][m]));
        acc[3][m] = fmaf(w3.x, hv.x, fmaf(w3.y, hv.y, acc[3][m]));
    }
    __syncwarp();
}

// K=32 term, 8 segments (merged encoder): warp takes 4 k columns.
__device__ __forceinline__ void term32w4(
    const float* __restrict__ x, int ld, const float* __restrict__ Wrow0,
    int seg, int lane, int bq, float acc[4][8], float* buf)
{
    const int kbase = seg * 4;
    __syncwarp();
    #pragma unroll
    for (int i = 0; i < 2; i++) {
        int b = lane + (i << 5);
        float4 v = __ldg((const float4*)(x + b * ld + kbase));
        *(float4*)(buf + b * BUFW) = v;
    }
    __syncwarp();
    float4 w0 = __ldg((const float4*)(Wrow0 + 0 * DIN + kbase));
    float4 w1 = __ldg((const float4*)(Wrow0 + 1 * DIN + kbase));
    float4 w2 = __ldg((const float4*)(Wrow0 + 2 * DIN + kbase));
    float4 w3 = __ldg((const float4*)(Wrow0 + 3 * DIN + kbase));
    #pragma unroll
    for (int m = 0; m < 8; m++) {
        float4 hv = *(const float4*)(buf + ((m << 3) + bq) * BUFW);
        acc[0][m] = fma4(w0, hv, acc[0][m]);
        acc[1][m] = fma4(w1, hv, acc[1][m]);
        acc[2][m] = fma4(w2, hv, acc[2][m]);
        acc[3][m] = fma4(w3, hv, acc[3][m]);
    }
    __syncwarp();
}

// ---- unmerged LSTM phase (decoder + encoder prologue/epilogue) ----
// 16 warps, 32-k slice each. KA in {0, 32, 512}; term B always K=512 (.cg).
__device__ __forceinline__ void lstm_phase(
    const float* xA, int ldA, const float* __restrict__ WA, int KA, bool cgA,
    const float* xB, const float* __restrict__ WB,
    const float* __restrict__ bih, const float* __restrict__ bhh,
    const float* __restrict__ b2,
    float* __restrict__ cst, float* __restrict__ hout, float* smem)
{
    const int tid  = threadIdx.x;
    const int w    = tid >> 5, lane = tid & 31;
    const int gate = lane >> 3, bq = lane & 7;
    float* buf = smem + w * BUFSZ;
    float* red = smem + REDBASE;

    float acc[4][8];
    #pragma unroll
    for (int r = 0; r < 4; r++)
        #pragma unroll
        for (int m = 0; m < 8; m++) acc[r][m] = 0.0f;

    const size_t rowbase = (size_t)((gate << 9) + (blockIdx.x << 2));
    if (KA == 32)
        term32w2(xA, ldA, WA + rowbase * DIN, w, lane, bq, acc, buf);
    const int nA = (KA == 512) ? 4 : 0;
    term_dual(xA, ldA, (KA == 512) ? WA + rowbase * H_ : WB + rowbase * H_, cgA, w * 32, nA,
              xB, H_, WB + rowbase * H_, true, w * 32, 4,
              lane, bq, acc, buf);

    #pragma unroll
    for (int rr = 0; rr < 4; rr++)
        #pragma unroll
        for (int m = 0; m < 8; m++)
            red[((gate << 2) + rr) * RROW + (w << 6) + (m << 3) + bq] = acc[rr][m];
    __syncthreads();

    if (tid < 256) {
        const int u = tid & 3, b = tid >> 2;
        const int ug = (blockIdx.x << 2) + u;
        float g4v[4];
        #pragma unroll
        for (int g = 0; g < 4; g++) {
            float s = 0.0f;
            #pragma unroll
            for (int s16 = 0; s16 < 16; s16++)
                s += red[((g << 2) + u) * RROW + (s16 << 6) + b];
            int r = (g << 9) + ug;
            s += __ldg(bih + r) + __ldg(bhh + r);
            if (b2) s += __ldg(b2 + r);
            g4v[g] = s;
        }
        const int idx = (b << 9) + ug;
        float cp = __ldcg(cst + idx);
        float cn = sigm(g4v[1]) * cp + sigm(g4v[0]) * tanhf(g4v[2]);
        __stcg(cst + idx, cn);
        __stcg(hout + idx, sigm(g4v[3]) * tanhf(cn));
    }
}

// ---- merged encoder phase t (1..1023): computes L1(t-1) AND L0(t) ----
// Warps 0-7: L0 tile (src(t)@eWih0 + h0(t-1)@eWhh0), 64-k slices.
// Warps 8-15: L1 tile (h0(t-1)@eWih1 + h1(t-2)@eWhh1), fused 128-k loop.
__device__ __forceinline__ void enc_merged(const P& p, int t, float* smem)
{
    const int tid  = threadIdx.x;
    const int w    = tid >> 5, lane = tid & 31;
    const int grp  = w >> 3, seg = w & 7;
    const int gate = lane >> 3, bq = lane & 7;
    float* buf = smem + w * BUFSZ;
    float* red = smem + REDBASE;

    float acc[4][8];
    #pragma unroll
    for (int r = 0; r < 4; r++)
        #pragma unroll
        for (int m = 0; m < 8; m++) acc[r][m] = 0.0f;

    const size_t rowbase = (size_t)((gate << 9) + (blockIdx.x << 2));
    const float* h0prev = gH0[(t - 1) & 1];     // h0(t-1)
    if (grp == 0) {
        term32w4(p.src + t * DIN, SLEN * DIN, p.eWih0 + rowbase * DIN,
                 seg, lane, bq, acc, buf);
        term_dual(h0prev, H_, p.eWhh0 + rowbase * H_, true, seg * 64, 8,
                  h0prev, H_, p.eWhh0 + rowbase * H_, true, seg * 64, 0,
                  lane, bq, acc, buf);
    } else {
        const float* h1prev2 = gH1[t & 1];      // h1(t-2) lives in buf t&1
        term_dual(h0prev,  H_, p.eWih1 + rowbase * H_, true, seg * 64, 8,
                  h1prev2, H_, p.eWhh1 + rowbase * H_, true, seg * 64, 8,
                  lane, bq, acc, buf);
    }

    #pragma unroll
    for (int rr = 0; rr < 4; rr++)
        #pragma unroll
        for (int m = 0; m < 8; m++)
            red[((grp << 4) + (gate << 2) + rr) * RROW2 + (seg << 6) + (m << 3) + bq] = acc[rr][m];
    __syncthreads();

    // finalize: 512 threads, one (layer, b, u) each
    {
        const int L = tid >> 8, rem = tid & 255;
        const int u = rem & 3, b = rem >> 2;
        const int ug = (blockIdx.x << 2) + u;
        const float* bih = L ? p.ebih1 : p.ebih0;
        const float* bhh = L ? p.ebhh1 : p.ebhh0;
        float g4v[4];
        #pragma unroll
        for (int g = 0; g < 4; g++) {
            float s = 0.0f;
            #pragma unroll
            for (int s8 = 0; s8 < 8; s8++)
                s += red[((L << 4) + (g << 2) + u) * RROW2 + (s8 << 6) + b];
            int r = (g << 9) + ug;
            s += __ldg(bih + r) + __ldg(bhh + r);
            g4v[g] = s;
        }
        float* cst  = L ? gC1 : gC0;
        float* hout = L ? gH1[(t - 1) & 1] : gH0[t & 1];
        const int idx = (b << 9) + ug;
        float cp = __ldcg(cst + idx);
        float cn = sigm(g4v[1]) * cp + sigm(g4v[0]) * tanhf(g4v[2]);
        __stcg(cst + idx, cn);
        __stcg(hout + idx, sigm(g4v[3]) * tanhf(cn));
    }
}

// pred(t) = h1 @ out_W.T + out_b -> d_out[:, t, :].
// Spread over ALL CTAs: 64 threads/CTA, 16 outputs/CTA.
__device__ __forceinline__ void do_pred(const P& p, const float* __restrict__ h1, int t)
{
    if (threadIdx.x >= 64) return;
    int g = (blockIdx.x << 6) + threadIdx.x;   // 0..8191
    int oid = g >> 2, part = g & 3;            // 2048 outputs, K split by 4
    int b = oid >> 5, j = oid & 31;
    const float* hr = h1 + (b << 9) + (part << 7);
    const float* wr = p.outW + (j << 9) + (part << 7);
    float s = 0.0f;
    #pragma unroll
    for (int k = 0; k < 128; k += 4) {
        float4 hv = __ldcg((const float4*)(hr + k));
        float4 wv = __ldg ((const float4*)(wr + k));
        s = fmaf(hv.x, wv.x, fmaf(hv.y, wv.y, fmaf(hv.z, wv.z, fmaf(hv.w, wv.w, s))));
    }
    s += __shfl_xor_sync(0xffffffffu, s, 1);
    s += __shfl_xor_sync(0xffffffffu, s, 2);
    if (part == 0)
        p.out[((long)b << 14) + (t << 5) + j] = s + __ldg(p.outB + j);
}

__global__ void __launch_bounds__(NT, 1) seq2seq_kernel(P p)
{
    extern __shared__ float smem[];
    const int gt = blockIdx.x * NT + threadIdx.x;   // 0..65535
    // Barrier epoch base: all flags are equal at kernel entry (monotonic,
    // fully synchronized at the end of the previous run / zero-initialized).
    unsigned bgen = ((volatile unsigned*)gFlag)[blockIdx.x];

    // ---- zero init: h(-1) lives in buffer 1 ----
    if (gt < B_ * H_) {
        __stcg(&gH0[1][gt], 0.0f);
        __stcg(&gH1[1][gt], 0.0f);
        __stcg(&gC0[gt],    0.0f);
        __stcg(&gC1[gt],    0.0f);
    }
    grid_bar(bgen);

    // ---- precompute M = dec_Wih0 @ out_W, b2 = dec_Wih0 @ out_b ----
    for (int o = gt; o < G4 * H_; o += NB * NT) {
        int rr = o >> 9, hc = o & 511;
        const float* wr = p.dWih0 + rr * DIN;
        const float* oc = p.outW + hc;
        float s = 0.0f;
        #pragma unroll
        for (int j = 0; j < DIN; j++) s = fmaf(__ldg(wr + j), __ldg(oc + j * H_), s);
        __stcg(&gM[o], s);
    }
    if (gt < G4) {
        const float* wr = p.dWih0 + gt * DIN;
        float s = 0.0f;
        #pragma unroll
        for (int j = 0; j < DIN; j++) s = fmaf(__ldg(wr + j), __ldg(p.outB + j), s);
        __stcg(&gB2[gt], s);
    }
    grid_bar(bgen);

    // ---- encoder ----
    // prologue: L0(0)   (reads h0(-1)=zeros in buf 1, writes h0(0) -> buf 0)
    lstm_phase(p.src, SLEN * DIN, p.eWih0, DIN, false,
               gH0[1], p.eWhh0,
               p.ebih0, p.ebhh0, nullptr, gC0, gH0[0], smem);
    grid_bar(bgen);
    // merged main loop: phase t computes L1(t-1) and L0(t)
    for (int t = 1; t < SLEN; t++) {
        enc_merged(p, t, smem);
        grid_bar(bgen);
    }
    // epilogue: L1(1023)  (h0(1023) in buf 1, h1(1022) in buf 0 -> h1(1023) buf 1)
    lstm_phase(gH0[1], H_, p.eWih1, H_, true,
               gH1[0], p.eWhh1,
               p.ebih1, p.ebhh1, nullptr, gC1, gH1[1], smem);
    grid_bar(bgen);

    // ---- decoder: 512 steps x 2 phases (+ pred side job, all CTAs) ----
    // h_dec(t) in buf t&1; h_dec(-1) = encoder finals in buf 1.
    for (int t = 0; t < TLEN; t++) {
        const int rp = (t - 1) & 1, wp = t & 1;
        lstm_phase(t ? gH1[rp] : nullptr, H_, gM, t ? H_ : 0, true,
                   gH0[rp], p.dWhh0,
                   p.dbih0, p.dbhh0, t ? gB2 : nullptr, gC0, gH0[wp], smem);
        if (t > 0) do_pred(p, gH1[rp], t - 1);
        grid_bar(bgen);
        lstm_phase(gH0[wp], H_, p.dWih1, H_, true,
                   gH1[rp], p.dWhh1,
                   p.dbih1, p.dbhh1, nullptr, gC1, gH1[wp], smem);
        grid_bar(bgen);
    }
    // final pred for t = TLEN-1 (h1(511) in buf 1)
    do_pred(p, gH1[1], TLEN - 1);
}

extern "C" void kernel_launch(void* const* d_in, const int* in_sizes, int n_in,
                              void* d_out, int out_size)
{
    const int o = (in_sizes[1] < 100) ? 1 : 0;   // skip target_length scalar if present

    P p;
    p.src   = (const float*)d_in[0];
    p.eWih0 = (const float*)d_in[1 + o];
    p.eWhh0 = (const float*)d_in[2 + o];
    p.ebih0 = (const float*)d_in[3 + o];
    p.ebhh0 = (const float*)d_in[4 + o];
    p.eWih1 = (const float*)d_in[5 + o];
    p.eWhh1 = (const float*)d_in[6 + o];
    p.ebih1 = (const float*)d_in[7 + o];
    p.ebhh1 = (const float*)d_in[8 + o];
    p.dWih0 = (const float*)d_in[9 + o];
    p.dWhh0 = (const float*)d_in[10 + o];
    p.dbih0 = (const float*)d_in[11 + o];
    p.dbhh0 = (const float*)d_in[12 + o];
    p.dWih1 = (const float*)d_in[13 + o];
    p.dWhh1 = (const float*)d_in[14 + o];
    p.dbih1 = (const float*)d_in[15 + o];
    p.dbhh1 = (const float*)d_in[16 + o];
    p.outW  = (const float*)d_in[17 + o];
    p.outB  = (const float*)d_in[18 + o];
    p.out   = (float*)d_out;

    cudaFuncSetAttribute(seq2seq_kernel,
                         cudaFuncAttributeMaxDynamicSharedMemorySize, SMEM_BYTES);
    seq2seq_kernel<<<NB, NT, SMEM_BYTES>>>(p);
}

// round 11
// speedup vs baseline: 1.2168x; 1.2168x over previous
#include <cuda_runtime.h>
#include <cuda_bf16.h>
#include <cstdint>
#include <math.h>

// ---------------------------------------------------------------------------
// Seq2Seq LSTM (B=64, S=1024, T=512, H=512, D_IN=D_OUT=32), fp32.
// Persistent kernel: 128 CTAs x 512 threads, flag grid barrier (CTA0 agg).
// Each CTA owns 16 gate-rows (4 units x 4 gates) x 64 batches per layer-tile.
// Encoder phases merged (L1(t-1)+L0(t) in one barrier). Decoder unmerged.
// Staging via cp.async.cg into a warp-private 3-slot ring (4-k chunks,
// depth-2 pipeline) -- no prefetch registers, no STS in the compute stream.
// Decoder feedback GEMM folded into precomputed gM = dec_Wih0 @ out_W.
// ---------------------------------------------------------------------------

typedef unsigned int u32;

#define NB   128
#define NT   512
#define B_    64
#define H_    512
#define G4   2048
#define DIN   32
#define SLEN 1024
#define TLEN  512
#define CHUNK  4                      // k per staged chunk

#define BUFSZ (3 * 256)               // 3 ring slots x (64 rows x 4 floats)
#define REDBASE (16 * BUFSZ)          // 12288 floats
#define RROW  1042                    // unmerged reduction row stride
#define RROW2 520                     // merged reduction row stride
#define SMEM_FLOATS (REDBASE + 16 * RROW)
#define SMEM_BYTES  (SMEM_FLOATS * 4)   // 115840 B

struct P {
    const float *src;
    const float *eWih0, *eWhh0, *ebih0, *ebhh0;
    const float *eWih1, *eWhh1, *ebih1, *ebhh1;
    const float *dWih0, *dWhh0, *dbih0, *dbhh0;
    const float *dWih1, *dWhh1, *dbih1, *dbhh1;
    const float *outW, *outB;
    float *out;
};

// ---- persistent state (device globals; allocation-free scratch) ----
__device__ float gH0[2][B_ * H_];
__device__ float gH1[2][B_ * H_];
__device__ float gC0[B_ * H_];
__device__ float gC1[B_ * H_];
__device__ float gM[G4 * H_];      // dec_Wih0 @ out_W   [2048 x 512]
__device__ float gB2[G4];          // dec_Wih0 @ out_b
__device__ unsigned gFlag[NB];     // monotonic per-CTA arrival counters
__device__ volatile unsigned g_gen = 0;

// Proven R6 barrier: CTA0's 128 threads poll the per-CTA flags; thread0
// publishes the new generation; other CTAs poll g_gen only.
__device__ __forceinline__ void grid_bar(unsigned &bgen) {
    __threadfence();
    __syncthreads();
    bgen++;
    if (blockIdx.x == 0) {
        if (threadIdx.x > 0 && threadIdx.x < NB) {
            volatile unsigned* f = gFlag + threadIdx.x;
            while (*f < bgen) __nanosleep(32);
        }
        __syncthreads();
        if (threadIdx.x == 0) { __threadfence(); g_gen = bgen; }
    } else {
        if (threadIdx.x == 0) {
            ((volatile unsigned*)gFlag)[blockIdx.x] = bgen;
            while (g_gen < bgen) __nanosleep(32);
        }
        __syncthreads();
    }
}

__device__ __forceinline__ float sigm(float x) { return 1.0f / (1.0f + expf(-x)); }

__device__ __forceinline__ float fma4(float4 a, float4 b, float s) {
    return fmaf(a.x, b.x, fmaf(a.y, b.y, fmaf(a.z, b.z, fmaf(a.w, b.w, s))));
}

// ---- cp.async helpers (L2-only .cg path: coherent with __stcg writes) ----
__device__ __forceinline__ void cpasync16(u32 saddr, const float* gptr) {
    asm volatile("cp.async.cg.shared.global [%0], [%1], 16;"
                 :: "r"(saddr), "l"(gptr) : "memory");
}
__device__ __forceinline__ void cpcommit() {
    asm volatile("cp.async.commit_group;" ::: "memory");
}
__device__ __forceinline__ void cpwait2() {
    asm volatile("cp.async.wait_group 2;" ::: "memory");
}

// Generic GEMM term over a K-slice: nch chunks of 4 k starting at kbase.
// acc[4 rows][8 batches]. W pre-offset to row 0, row stride WS (template).
// x: [64 rows, stride ld]. 3-slot smem ring, depth-2 cp.async pipeline.
// Group discipline: preamble commits exactly 2 groups; each iteration
// commits exactly 1 (possibly empty) -> wait_group 2 at iter c guarantees
// chunk c's data has landed for every lane (followed by a syncwarp).
template<int WS>
__device__ __forceinline__ void termK(
    const float* x, int ld, const float* __restrict__ W,
    int kbase, int nch, int lane, int bq, float acc[4][8],
    const float* buf, u32 bufa)
{
    const float* xr0 = x + (size_t)lane * ld + kbase;
    const float* xr1 = x + (size_t)(lane + 32) * ld + kbase;
    const u32 a0 = bufa + lane * 16;
    const u32 a1 = bufa + (lane + 32) * 16;

    // preamble: issue up to 2 chunks, pad to exactly 2 committed groups
    const int pre = (nch < 2) ? nch : 2;
    for (int c = 0; c < pre; c++) {
        const u32 s = (u32)((c % 3) * 1024);
        cpasync16(a0 + s, xr0 + c * CHUNK);
        cpasync16(a1 + s, xr1 + c * CHUNK);
        cpcommit();
    }
    for (int c = pre; c < 2; c++) cpcommit();

    for (int c = 0; c < nch; c++) {
        if (c + 2 < nch) {
            const u32 s = (u32)(((c + 2) % 3) * 1024);
            cpasync16(a0 + s, xr0 + (c + 2) * CHUNK);
            cpasync16(a1 + s, xr1 + (c + 2) * CHUNK);
        }
        cpcommit();
        cpwait2();
        __syncwarp();                    // all lanes' chunk-c data visible
        const float* hb = buf + (c % 3) * 256 + bq * 4;
        const float* wb = W + kbase + c * CHUNK;
        float4 w0 = __ldg((const float4*)(wb + 0 * WS));
        float4 w1 = __ldg((const float4*)(wb + 1 * WS));
        float4 w2 = __ldg((const float4*)(wb + 2 * WS));
        float4 w3 = __ldg((const float4*)(wb + 3 * WS));
        #pragma unroll
        for (int m = 0; m < 8; m++) {
            float4 hv = *(const float4*)(hb + m * 32);   // rows m*8+bq, stride 4
            acc[0][m] = fma4(w0, hv, acc[0][m]);
            acc[1][m] = fma4(w1, hv, acc[1][m]);
            acc[2][m] = fma4(w2, hv, acc[2][m]);
            acc[3][m] = fma4(w3, hv, acc[3][m]);
        }
        __syncwarp();                    // slot c%3 free before c+3 issues
    }
}

// ---- unmerged LSTM phase (decoder + encoder prologue/epilogue) ----
// 16 warps, 32-k slice each per term. KA in {0, 32, 512}; term B K=512.
__device__ __forceinline__ void lstm_phase(
    const float* xA, int ldA, const float* __restrict__ WA, int KA,
    const float* xB, const float* __restrict__ WB,
    const float* __restrict__ bih, const float* __restrict__ bhh,
    const float* __restrict__ b2,
    float* __restrict__ cst, float* __restrict__ hout,
    float* smem, u32 smema)
{
    const int tid  = threadIdx.x;
    const int w    = tid >> 5, lane = tid & 31;
    const int gate = lane >> 3, bq = lane & 7;
    float* buf = smem + w * BUFSZ;
    const u32 bufa = smema + (u32)(w * BUFSZ * 4);
    float* red = smem + REDBASE;

    float acc[4][8];
    #pragma unroll
    for (int r = 0; r < 4; r++)
        #pragma unroll
        for (int m = 0; m < 8; m++) acc[r][m] = 0.0f;

    const size_t rowbase = (size_t)((gate << 9) + (blockIdx.x << 2));
    if (KA == 512)
        termK<512>(xA, ldA, WA + rowbase * H_, w * 32, 8, lane, bq, acc, buf, bufa);
    else if (KA == 32 && w < 8)
        termK<32>(xA, ldA, WA + rowbase * DIN, w * 4, 1, lane, bq, acc, buf, bufa);
    termK<512>(xB, H_, WB + rowbase * H_, w * 32, 8, lane, bq, acc, buf, bufa);

    #pragma unroll
    for (int rr = 0; rr < 4; rr++)
        #pragma unroll
        for (int m = 0; m < 8; m++)
            red[((gate << 2) + rr) * RROW + (w << 6) + (m << 3) + bq] = acc[rr][m];
    __syncthreads();

    if (tid < 256) {
        const int u = tid & 3, b = tid >> 2;
        const int ug = (blockIdx.x << 2) + u;
        float g4v[4];
        #pragma unroll
        for (int g = 0; g < 4; g++) {
            float s = 0.0f;
            #pragma unroll
            for (int s16 = 0; s16 < 16; s16++)
                s += red[((g << 2) + u) * RROW + (s16 << 6) + b];
            int r = (g << 9) + ug;
            s += __ldg(bih + r) + __ldg(bhh + r);
            if (b2) s += __ldg(b2 + r);
            g4v[g] = s;
        }
        const int idx = (b << 9) + ug;
        float cp = __ldcg(cst + idx);
        float cn = sigm(g4v[1]) * cp + sigm(g4v[0]) * tanhf(g4v[2]);
        __stcg(cst + idx, cn);
        __stcg(hout + idx, sigm(g4v[3]) * tanhf(cn));
    }
}

// ---- merged encoder phase t (1..1023): computes L1(t-1) AND L0(t) ----
// Warps 0-7: L0 tile (src(t)@eWih0 + h0(t-1)@eWhh0), 64-k slices.
// Warps 8-15: L1 tile (h0(t-1)@eWih1 + h1(t-2)@eWhh1), 64-k slices.
__device__ __forceinline__ void enc_merged(const P& p, int t,
                                           float* smem, u32 smema)
{
    const int tid  = threadIdx.x;
    const int w    = tid >> 5, lane = tid & 31;
    const int grp  = w >> 3, seg = w & 7;
    const int gate = lane >> 3, bq = lane & 7;
    float* buf = smem + w * BUFSZ;
    const u32 bufa = smema + (u32)(w * BUFSZ * 4);
    float* red = smem + REDBASE;

    float acc[4][8];
    #pragma unroll
    for (int r = 0; r < 4; r++)
        #pragma unroll
        for (int m = 0; m < 8; m++) acc[r][m] = 0.0f;

    const size_t rowbase = (size_t)((gate << 9) + (blockIdx.x << 2));
    const float* h0prev = gH0[(t - 1) & 1];     // h0(t-1)
    if (grp == 0) {
        termK<32>(p.src + t * DIN, SLEN * DIN, p.eWih0 + rowbase * DIN,
                  seg * 4, 1, lane, bq, acc, buf, bufa);
        termK<512>(h0prev, H_, p.eWhh0 + rowbase * H_,
                   seg * 64, 16, lane, bq, acc, buf, bufa);
    } else {
        const float* h1prev2 = gH1[t & 1];      // h1(t-2) lives in buf t&1
        termK<512>(h0prev,  H_, p.eWih1 + rowbase * H_,
                   seg * 64, 16, lane, bq, acc, buf, bufa);
        termK<512>(h1prev2, H_, p.eWhh1 + rowbase * H_,
                   seg * 64, 16, lane, bq, acc, buf, bufa);
    }

    #pragma unroll
    for (int rr = 0; rr < 4; rr++)
        #pragma unroll
        for (int m = 0; m < 8; m++)
            red[((grp << 4) + (gate << 2) + rr) * RROW2 + (seg << 6) + (m << 3) + bq] = acc[rr][m];
    __syncthreads();

    // finalize: 512 threads, one (layer, b, u) each
    {
        const int L = tid >> 8, rem = tid & 255;
        const int u = rem & 3, b = rem >> 2;
        const int ug = (blockIdx.x << 2) + u;
        const float* bih = L ? p.ebih1 : p.ebih0;
        const float* bhh = L ? p.ebhh1 : p.ebhh0;
        float g4v[4];
        #pragma unroll
        for (int g = 0; g < 4; g++) {
            float s = 0.0f;
            #pragma unroll
            for (int s8 = 0; s8 < 8; s8++)
                s += red[((L << 4) + (g << 2) + u) * RROW2 + (s8 << 6) + b];
            int r = (g << 9) + ug;
            s += __ldg(bih + r) + __ldg(bhh + r);
            g4v[g] = s;
        }
        float* cst  = L ? gC1 : gC0;
        float* hout = L ? gH1[(t - 1) & 1] : gH0[t & 1];
        const int idx = (b << 9) + ug;
        float cp = __ldcg(cst + idx);
        float cn = sigm(g4v[1]) * cp + sigm(g4v[0]) * tanhf(g4v[2]);
        __stcg(cst + idx, cn);
        __stcg(hout + idx, sigm(g4v[3]) * tanhf(cn));
    }
}

// pred(t) = h1 @ out_W.T + out_b -> d_out[:, t, :].
// Spread over ALL CTAs: 64 threads/CTA, 16 outputs/CTA.
__device__ __forceinline__ void do_pred(const P& p, const float* __restrict__ h1, int t)
{
    if (threadIdx.x >= 64) return;
    int g = (blockIdx.x << 6) + threadIdx.x;   // 0..8191
    int oid = g >> 2, part = g & 3;            // 2048 outputs, K split by 4
    int b = oid >> 5, j = oid & 31;
    const float* hr = h1 + (b << 9) + (part << 7);
    const float* wr = p.outW + (j << 9) + (part << 7);
    float s = 0.0f;
    #pragma unroll
    for (int k = 0; k < 128; k += 4) {
        float4 hv = __ldcg((const float4*)(hr + k));
        float4 wv = __ldg ((const float4*)(wr + k));
        s = fmaf(hv.x, wv.x, fmaf(hv.y, wv.y, fmaf(hv.z, wv.z, fmaf(hv.w, wv.w, s))));
    }
    s += __shfl_xor_sync(0xffffffffu, s, 1);
    s += __shfl_xor_sync(0xffffffffu, s, 2);
    if (part == 0)
        p.out[((long)b << 14) + (t << 5) + j] = s + __ldg(p.outB + j);
}

__global__ void __launch_bounds__(NT, 1) seq2seq_kernel(P p)
{
    extern __shared__ float smem[];
    const u32 smema = (u32)__cvta_generic_to_shared(smem);
    const int gt = blockIdx.x * NT + threadIdx.x;   // 0..65535
    unsigned bgen = g_gen;                          // monotonic barrier epoch

    // ---- zero init: h(-1) lives in buffer 1 ----
    if (gt < B_ * H_) {
        __stcg(&gH0[1][gt], 0.0f);
        __stcg(&gH1[1][gt], 0.0f);
        __stcg(&gC0[gt],    0.0f);
        __stcg(&gC1[gt],    0.0f);
    }
    grid_bar(bgen);

    // ---- precompute M = dec_Wih0 @ out_W, b2 = dec_Wih0 @ out_b ----
    for (int o = gt; o < G4 * H_; o += NB * NT) {
        int rr = o >> 9, hc = o & 511;
        const float* wr = p.dWih0 + rr * DIN;
        const float* oc = p.outW + hc;
        float s = 0.0f;
        #pragma unroll
        for (int j = 0; j < DIN; j++) s = fmaf(__ldg(wr + j), __ldg(oc + j * H_), s);
        __stcg(&gM[o], s);
    }
    if (gt < G4) {
        const float* wr = p.dWih0 + gt * DIN;
        float s = 0.0f;
        #pragma unroll
        for (int j = 0; j < DIN; j++) s = fmaf(__ldg(wr + j), __ldg(p.outB + j), s);
        __stcg(&gB2[gt], s);
    }
    grid_bar(bgen);

    // ---- encoder ----
    // prologue: L0(0)   (reads h0(-1)=zeros in buf 1, writes h0(0) -> buf 0)
    lstm_phase(p.src, SLEN * DIN, p.eWih0, DIN,
               gH0[1], p.eWhh0,
               p.ebih0, p.ebhh0, nullptr, gC0, gH0[0], smem, smema);
    grid_bar(bgen);
    // merged main loop: phase t computes L1(t-1) and L0(t)
    for (int t = 1; t < SLEN; t++) {
        enc_merged(p, t, smem, smema);
        grid_bar(bgen);
    }
    // epilogue: L1(1023)  (h0(1023) in buf 1, h1(1022) in buf 0 -> h1(1023) buf 1)
    lstm_phase(gH0[1], H_, p.eWih1, H_,
               gH1[0], p.eWhh1,
               p.ebih1, p.ebhh1, nullptr, gC1, gH1[1], smem, smema);
    grid_bar(bgen);

    // ---- decoder: 512 steps x 2 phases (+ pred side job, all CTAs) ----
    // h_dec(t) in buf t&1; h_dec(-1) = encoder finals in buf 1.
    for (int t = 0; t < TLEN; t++) {
        const int rp = (t - 1) & 1, wp = t & 1;
        lstm_phase(t ? gH1[rp] : nullptr, H_, gM, t ? 512 : 0,
                   gH0[rp], p.dWhh0,
                   p.dbih0, p.dbhh0, t ? gB2 : nullptr, gC0, gH0[wp], smem, smema);
        if (t > 0) do_pred(p, gH1[rp], t - 1);
        grid_bar(bgen);
        lstm_phase(gH0[wp], H_, p.dWih1, H_,
                   gH1[rp], p.dWhh1,
                   p.dbih1, p.dbhh1, nullptr, gC1, gH1[wp], smem, smema);
        grid_bar(bgen);
    }
    // final pred for t = TLEN-1 (h1(511) in buf 1)
    do_pred(p, gH1[1], TLEN - 1);
}

extern "C" void kernel_launch(void* const* d_in, const int* in_sizes, int n_in,
                              void* d_out, int out_size)
{
    const int o = (in_sizes[1] < 100) ? 1 : 0;   // skip target_length scalar if present

    P p;
    p.src   = (const float*)d_in[0];
    p.eWih0 = (const float*)d_in[1 + o];
    p.eWhh0 = (const float*)d_in[2 + o];
    p.ebih0 = (const float*)d_in[3 + o];
    p.ebhh0 = (const float*)d_in[4 + o];
    p.eWih1 = (const float*)d_in[5 + o];
    p.eWhh1 = (const float*)d_in[6 + o];
    p.ebih1 = (const float*)d_in[7 + o];
    p.ebhh1 = (const float*)d_in[8 + o];
    p.dWih0 = (const float*)d_in[9 + o];
    p.dWhh0 = (const float*)d_in[10 + o];
    p.dbih0 = (const float*)d_in[11 + o];
    p.dbhh0 = (const float*)d_in[12 + o];
    p.dWih1 = (const float*)d_in[13 + o];
    p.dWhh1 = (const float*)d_in[14 + o];
    p.dbih1 = (const float*)d_in[15 + o];
    p.dbhh1 = (const float*)d_in[16 + o];
    p.outW  = (const float*)d_in[17 + o];
    p.outB  = (const float*)d_in[18 + o];
    p.out   = (float*)d_out;

    cudaFuncSetAttribute(seq2seq_kernel,
                         cudaFuncAttributeMaxDynamicSharedMemorySize, SMEM_BYTES);
    seq2seq_kernel<<<NB, NT, SMEM_BYTES>>>(p);
}